// round 14
// baseline (speedup 1.0000x reference)
#include <cuda_runtime.h>

#define NN 50000
#define EE 800000
#define FF 602
#define HH 32
#define CC 41
#define BN_EPS 1e-5f
#define FULLMASK 0xffffffffu
#define NB_SCAN ((NN + 255) / 256)   // 196
#define GRID_CSR 592                  // persistent csr2 grid
#define GRID_GIN 592                  // persistent gins grid (4 blocks/SM)

#define KC 16                         // k-chunk for gemm1
#define GT2 64                        // rows per gemm1 block
#define XP 68                         // 64 + pad

#define NPB 64                        // nodes per gin/head tile
#define NB_GIN ((NN + NPB - 1) / NPB) // 782

// ---------------- scratch (device globals) ----------------------------------
static __device__ float d_y  [NN * HH];
static __device__ float d_h1 [NN * HH];
static __device__ float d_h2 [NN * HH];
static __device__ float d_stats[4 * HH];
static __device__ int   d_counts[NN];     // re-zeroed by k_gins phase3 (BSS=0 first call)
static __device__ int   d_rowptr[NN];
static __device__ int   d_cursor[NN];
static __device__ int   d_colsorted[EE];  // stores c*HH (pre-scaled)
static __device__ int   d_partsum[256];
static __device__ int   d_partflag[256];  // re-zeroed by k_gins phase3
static __device__ int   d_barC;           // csr2 ticket barrier (never reset)
static __device__ int   d_barA;           // gins ticket barrier 1 (never reset)
static __device__ int   d_barB;           // gins ticket barrier 2 (never reset)

// ---------------- ticket grid barrier (replay-safe, no reset) ----------------
__device__ __forceinline__ void grid_bar(int* cnt, int nblk) {
    __syncthreads();
    if (threadIdx.x == 0) {
        __threadfence();
        int ticket = atomicAdd(cnt, 1);
        int target = (ticket / nblk + 1) * nblk;
        while (((volatile int*)cnt)[0] < target) { }
        __threadfence();
    }
    __syncthreads();
}

// ---------------- K1: y = x @ W1a — 4x4 tile, double-buffered (round-11) ----
__global__ void __launch_bounds__(128) k_gemm1(const float* __restrict__ x,
                                               const float* __restrict__ W1a) {
    __shared__ float xs[2][KC][XP];
    __shared__ float Ws[2][KC][HH];

    const int tid = threadIdx.x;
    const int rg  = tid >> 3;
    const int cg  = (tid & 7) * 4;
    const int rowbase = blockIdx.x * GT2;

    const int kl = tid & 15;
    const int rl = tid >> 4;
    const int wk = tid >> 3;
    const int wc = (tid & 7) * 4;

    float acc[4][4];
#pragma unroll
    for (int i = 0; i < 4; i++)
#pragma unroll
        for (int j = 0; j < 4; j++) acc[i][j] = 0.f;

    float xr[8];
    float4 wr;

    {
        const bool kok = kl < FF;
#pragma unroll
        for (int p = 0; p < 8; p++) {
            int grow = rowbase + rl * 8 + p;
            xr[p] = (kok && grow < NN) ? x[(size_t)grow * FF + kl] : 0.f;
        }
        wr = (wk < FF) ? *(const float4*)&W1a[wk * HH + wc]
                       : make_float4(0.f, 0.f, 0.f, 0.f);
#pragma unroll
        for (int p = 0; p < 8; p++) xs[0][kl][rl * 8 + p] = xr[p];
        *(float4*)&Ws[0][wk][wc] = wr;
    }
    __syncthreads();

    int buf = 0;
    for (int kb = 0; kb < FF; kb += KC) {
        const int nb = kb + KC;
        const bool hasnext = nb < FF;
        if (hasnext) {
            const bool kok = (nb + kl) < FF;
#pragma unroll
            for (int p = 0; p < 8; p++) {
                int grow = rowbase + rl * 8 + p;
                xr[p] = (kok && grow < NN) ? x[(size_t)grow * FF + nb + kl] : 0.f;
            }
            wr = ((nb + wk) < FF) ? *(const float4*)&W1a[(nb + wk) * HH + wc]
                                  : make_float4(0.f, 0.f, 0.f, 0.f);
        }
#pragma unroll
        for (int k = 0; k < KC; k++) {
            float4 xv = *(const float4*)&xs[buf][k][rg * 4];
            float4 wv = *(const float4*)&Ws[buf][k][cg];
            acc[0][0] += xv.x * wv.x; acc[0][1] += xv.x * wv.y;
            acc[0][2] += xv.x * wv.z; acc[0][3] += xv.x * wv.w;
            acc[1][0] += xv.y * wv.x; acc[1][1] += xv.y * wv.y;
            acc[1][2] += xv.y * wv.z; acc[1][3] += xv.y * wv.w;
            acc[2][0] += xv.z * wv.x; acc[2][1] += xv.z * wv.y;
            acc[2][2] += xv.z * wv.z; acc[2][3] += xv.z * wv.w;
            acc[3][0] += xv.w * wv.x; acc[3][1] += xv.w * wv.y;
            acc[3][2] += xv.w * wv.z; acc[3][3] += xv.w * wv.w;
        }
        if (hasnext) {
            int nbuf = buf ^ 1;
#pragma unroll
            for (int p = 0; p < 8; p++) xs[nbuf][kl][rl * 8 + p] = xr[p];
            *(float4*)&Ws[nbuf][wk][wc] = wr;
            __syncthreads();
            buf = nbuf;
        }
    }
#pragma unroll
    for (int i = 0; i < 4; i++) {
        int row = rowbase + rg * 4 + i;
        if (row < NN)
            *(float4*)&d_y[(size_t)row * HH + cg] =
                make_float4(acc[i][0], acc[i][1], acc[i][2], acc[i][3]);
    }
}

// ---------------- CSR: hist (1 edge/thread) ----------------------------------
__global__ void k_hist(const int* __restrict__ row) {
    int e = blockIdx.x * 256 + threadIdx.x;
    if (e < EE) atomicAdd(&d_counts[row[e]], 1);
}

// ---------------- CSR: merged scan + scatter (persistent) --------------------
__global__ void __launch_bounds__(256) k_csr2(const int* __restrict__ row,
                                              const int* __restrict__ col) {
    __shared__ int sh[256];
    __shared__ int red[8];
    __shared__ int s_boff;
    const int tid = threadIdx.x, blk = blockIdx.x;

    if (blk < NB_SCAN) {
        if (blk == 0 && tid < 4 * HH) d_stats[tid] = 0.f;

        int i = blk * 256 + tid;
        int c = (i < NN) ? d_counts[i] : 0;
        sh[tid] = c;
        __syncthreads();
        for (int off = 1; off < 256; off <<= 1) {
            int t = (tid >= off) ? sh[tid - off] : 0;
            __syncthreads();
            sh[tid] += t;
            __syncthreads();
        }
        if (tid == 0) {
            d_partsum[blk] = sh[255];
            __threadfence();
            d_partflag[blk] = 1;
        }
        int acc = 0;
        for (int b = tid; b < blk; b += 256) {
            while (((volatile int*)d_partflag)[b] == 0) { }
            acc += ((volatile int*)d_partsum)[b];
        }
#pragma unroll
        for (int off = 16; off > 0; off >>= 1)
            acc += __shfl_down_sync(FULLMASK, acc, off);
        if ((tid & 31) == 0) red[tid >> 5] = acc;
        __syncthreads();
        if (tid == 0) {
            int t = 0;
#pragma unroll
            for (int w = 0; w < 8; w++) t += red[w];
            s_boff = t;
        }
        __syncthreads();
        int start = s_boff + sh[tid] - c;
        if (i < NN) { d_rowptr[i] = start; d_cursor[i] = start; }
    }

    grid_bar(&d_barC, GRID_CSR);

    // scatter: store column PRE-SCALED by HH
    for (int e = blk * 256 + tid; e < EE; e += GRID_CSR * 256) {
        int r = row[e];
        int c = col[e];
        int p = atomicAdd(&d_cursor[r], 1);
        d_colsorted[p] = c * HH;
    }
}

// ---------------- vectorized gather: 4 edges/step, float4 lanes --------------
// lanes: g = lane>>3 (edge slot), q4 = (lane&7)*4 (feature offset).
// Returns group-reduced float4 (features q4..q4+3), identical on all g.
__device__ __forceinline__ float4 gather_vec4(const float* __restrict__ src,
                                              int s0, int deg, int lane) {
    const int g  = lane >> 3;
    const int q4 = (lane & 7) << 2;
    float4 acc = make_float4(0.f, 0.f, 0.f, 0.f);
    for (int e0 = 0; e0 < deg; e0 += 32) {
        int rem = deg - e0;
        if (rem > 32) rem = 32;
        int idx = (lane < rem) ? d_colsorted[s0 + e0 + lane] : 0;  // pre-scaled c*HH
        for (int j = 0; j < rem; j += 4) {
            int c = __shfl_sync(FULLMASK, idx, j + g);
            if (j + g < rem) {
                float4 v = *(const float4*)(src + c + q4);
                acc.x += v.x; acc.y += v.y; acc.z += v.z; acc.w += v.w;
            }
        }
    }
#pragma unroll
    for (int off = 8; off <= 16; off <<= 1) {
        acc.x += __shfl_xor_sync(FULLMASK, acc.x, off);
        acc.y += __shfl_xor_sync(FULLMASK, acc.y, off);
        acc.z += __shfl_xor_sync(FULLMASK, acc.z, off);
        acc.w += __shfl_xor_sync(FULLMASK, acc.w, off);
    }
    return acc;
}

// tiled matvec: thread owns (node nl, cols cg..cg+7), weights stride 48
__device__ __forceinline__ void matmul8(const float (*zst)[NPB + 1],
                                        const float (*Ws)[48],
                                        int nl, int cg, float o[8]) {
#pragma unroll
    for (int k = 0; k < HH; k++) {
        float zv = zst[k][nl];
        float4 w0 = *(const float4*)&Ws[k][cg];
        float4 w1 = *(const float4*)&Ws[k][cg + 4];
        o[0] += zv * w0.x; o[1] += zv * w0.y;
        o[2] += zv * w0.z; o[3] += zv * w0.w;
        o[4] += zv * w1.x; o[5] += zv * w1.y;
        o[6] += zv * w1.z; o[7] += zv * w1.w;
    }
}

// ---------------- fused gin1 -> gin2 -> head (persistent) --------------------
__global__ void __launch_bounds__(256, 4) k_gins(
    const float* __restrict__ b1a, const float* __restrict__ W1b,
    const float* __restrict__ b1b,
    const float* __restrict__ g1,  const float* __restrict__ be1,
    const float* __restrict__ W2a, const float* __restrict__ b2a,
    const float* __restrict__ W2b, const float* __restrict__ b2b,
    const float* __restrict__ g2,  const float* __restrict__ be2,
    const float* __restrict__ Wf1, const float* __restrict__ bf1,
    const float* __restrict__ Wf2, const float* __restrict__ bf2,
    float* __restrict__ outp) {
    __shared__ float zst[HH][NPB + 1];
    __shared__ float ust[HH][NPB + 1];
    __shared__ __align__(16) float WA[HH][48];
    __shared__ __align__(16) float WB[HH][48];
    __shared__ float redS[8][HH], redQ[8][HH];
    __shared__ float scl[HH], shf[HH];

    const int tid  = threadIdx.x;
    const int blk  = blockIdx.x;
    const int warp = tid >> 5, lane = tid & 31;
    const int g    = lane >> 3;
    const int q4   = (lane & 7) << 2;
    const int nl   = tid >> 2;
    const int cg   = (tid & 3) * 8;

    // ================= PHASE 1: conv1 =================
    for (int i = tid; i < HH * HH; i += 256) WB[i >> 5][i & 31] = W1b[i];
    __syncthreads();

    for (int t = blk; t < NB_GIN; t += GRID_GIN) {
        const int base = t * NPB;
        // staging: warp handles 8 nodes
        {
            float4 ba4 = *(const float4*)&b1a[q4];
#pragma unroll
            for (int i = 0; i < 8; i++) {
                int nloc = warp * 8 + i;
                int n = base + nloc;
                float4 z = make_float4(0.f, 0.f, 0.f, 0.f);
                if (n < NN) {
                    int s0 = d_rowptr[n], deg = d_counts[n];
                    float4 acc = gather_vec4(d_y, s0, deg, lane);
                    float4 self = *(const float4*)&d_y[(size_t)n * HH + q4];
                    z.x = fmaxf(self.x + acc.x + ba4.x, 0.f);
                    z.y = fmaxf(self.y + acc.y + ba4.y, 0.f);
                    z.z = fmaxf(self.z + acc.z + ba4.z, 0.f);
                    z.w = fmaxf(self.w + acc.w + ba4.w, 0.f);
                }
                if (g == 0) {
                    zst[q4 + 0][nloc] = z.x; zst[q4 + 1][nloc] = z.y;
                    zst[q4 + 2][nloc] = z.z; zst[q4 + 3][nloc] = z.w;
                }
            }
        }
        __syncthreads();

        const int n = base + nl;
        const bool valid = n < NN;
        float o[8];
        {
            float4 b0 = *(const float4*)&b1b[cg];
            float4 b1 = *(const float4*)&b1b[cg + 4];
            o[0] = b0.x; o[1] = b0.y; o[2] = b0.z; o[3] = b0.w;
            o[4] = b1.x; o[5] = b1.y; o[6] = b1.z; o[7] = b1.w;
        }
        matmul8(zst, WB, nl, cg, o);
        if (valid) {
            *(float4*)&d_h1[(size_t)n * HH + cg]     = make_float4(o[0], o[1], o[2], o[3]);
            *(float4*)&d_h1[(size_t)n * HH + cg + 4] = make_float4(o[4], o[5], o[6], o[7]);
        }
        // stats
        {
            float s[8], q[8];
#pragma unroll
            for (int j = 0; j < 8; j++) {
                float v = valid ? o[j] : 0.f;
                s[j] = v; q[j] = v * v;
            }
#pragma unroll
            for (int off = 16; off >= 4; off >>= 1)
#pragma unroll
                for (int j = 0; j < 8; j++) {
                    s[j] += __shfl_down_sync(FULLMASK, s[j], off);
                    q[j] += __shfl_down_sync(FULLMASK, q[j], off);
                }
            if (lane < 4) {
#pragma unroll
                for (int j = 0; j < 8; j++) {
                    redS[warp][lane * 8 + j] = s[j];
                    redQ[warp][lane * 8 + j] = q[j];
                }
            }
            __syncthreads();
            if (warp == 0) {
                float ts = 0.f, tq = 0.f;
#pragma unroll
                for (int w = 0; w < 8; w++) { ts += redS[w][lane]; tq += redQ[w][lane]; }
                atomicAdd(&d_stats[lane],      ts);
                atomicAdd(&d_stats[HH + lane], tq);
            }
            __syncthreads();
        }
    }

    grid_bar(&d_barA, GRID_GIN);

    // ================= PHASE 2: conv2 =================
    for (int i = tid; i < HH * HH; i += 256) {
        WA[i >> 5][i & 31] = W2a[i];
        WB[i >> 5][i & 31] = W2b[i];
    }
    if (tid < HH) {
        float m = d_stats[tid] * (1.f / NN);
        float v = d_stats[HH + tid] * (1.f / NN) - m * m;
        float s = g1[tid] * rsqrtf(v + BN_EPS);
        scl[tid] = s;
        shf[tid] = be1[tid] - m * s;
    }
    __syncthreads();

    for (int t = blk; t < NB_GIN; t += GRID_GIN) {
        const int base = t * NPB;
        {
            float4 sc4 = *(const float4*)&scl[q4];
            float4 sh4 = *(const float4*)&shf[q4];
#pragma unroll
            for (int i = 0; i < 8; i++) {
                int nloc = warp * 8 + i;
                int n = base + nloc;
                float4 z = make_float4(0.f, 0.f, 0.f, 0.f);
                if (n < NN) {
                    int s0 = d_rowptr[n], deg = d_counts[n];
                    float4 acc = gather_vec4(d_h1, s0, deg, lane);
                    float4 self = *(const float4*)&d_h1[(size_t)n * HH + q4];
                    float fd = (float)(deg + 1);
                    z.x = (self.x + acc.x) * sc4.x + fd * sh4.x;
                    z.y = (self.y + acc.y) * sc4.y + fd * sh4.y;
                    z.z = (self.z + acc.z) * sc4.z + fd * sh4.z;
                    z.w = (self.w + acc.w) * sc4.w + fd * sh4.w;
                }
                if (g == 0) {
                    zst[q4 + 0][nloc] = z.x; zst[q4 + 1][nloc] = z.y;
                    zst[q4 + 2][nloc] = z.z; zst[q4 + 3][nloc] = z.w;
                }
            }
        }
        __syncthreads();

        const int n = base + nl;
        const bool valid = n < NN;
        float u[8];
        {
            float4 b0 = *(const float4*)&b2a[cg];
            float4 b1 = *(const float4*)&b2a[cg + 4];
            u[0] = b0.x; u[1] = b0.y; u[2] = b0.z; u[3] = b0.w;
            u[4] = b1.x; u[5] = b1.y; u[6] = b1.z; u[7] = b1.w;
        }
        matmul8(zst, WA, nl, cg, u);
#pragma unroll
        for (int j = 0; j < 8; j++) {
            u[j] = fmaxf(u[j], 0.f);
            ust[cg + j][nl] = u[j];
        }
        __syncthreads();

        float o[8];
        {
            float4 b0 = *(const float4*)&b2b[cg];
            float4 b1 = *(const float4*)&b2b[cg + 4];
            o[0] = b0.x; o[1] = b0.y; o[2] = b0.z; o[3] = b0.w;
            o[4] = b1.x; o[5] = b1.y; o[6] = b1.z; o[7] = b1.w;
        }
        matmul8(ust, WB, nl, cg, o);
        if (valid) {
            *(float4*)&d_h2[(size_t)n * HH + cg]     = make_float4(o[0], o[1], o[2], o[3]);
            *(float4*)&d_h2[(size_t)n * HH + cg + 4] = make_float4(o[4], o[5], o[6], o[7]);
        }
        {
            float s[8], q[8];
#pragma unroll
            for (int j = 0; j < 8; j++) {
                float v = valid ? o[j] : 0.f;
                s[j] = v; q[j] = v * v;
            }
#pragma unroll
            for (int off = 16; off >= 4; off >>= 1)
#pragma unroll
                for (int j = 0; j < 8; j++) {
                    s[j] += __shfl_down_sync(FULLMASK, s[j], off);
                    q[j] += __shfl_down_sync(FULLMASK, q[j], off);
                }
            if (lane < 4) {
#pragma unroll
                for (int j = 0; j < 8; j++) {
                    redS[warp][lane * 8 + j] = s[j];
                    redQ[warp][lane * 8 + j] = q[j];
                }
            }
            __syncthreads();
            if (warp == 0) {
                float ts = 0.f, tq = 0.f;
#pragma unroll
                for (int w = 0; w < 8; w++) { ts += redS[w][lane]; tq += redQ[w][lane]; }
                atomicAdd(&d_stats[2 * HH + lane], ts);
                atomicAdd(&d_stats[3 * HH + lane], tq);
            }
            __syncthreads();
        }
    }

    grid_bar(&d_barB, GRID_GIN);

    // ================= PHASE 3: head + CSR-state reset =================
    for (int i = blk * 256 + tid; i < NN; i += GRID_GIN * 256) d_counts[i] = 0;
    if (blk == 0 && tid < 256) d_partflag[tid] = 0;

    for (int i = tid; i < HH * HH; i += 256) WA[i >> 5][i & 31] = Wf1[i];
    for (int i = tid; i < HH * 48; i += 256) {
        int k = i / 48, c = i % 48;
        WB[k][c] = (c < CC) ? Wf2[k * CC + c] : 0.f;
    }
    if (tid < HH) {
        float m = d_stats[2 * HH + tid] * (1.f / NN);
        float v = d_stats[3 * HH + tid] * (1.f / NN) - m * m;
        float s = g2[tid] * rsqrtf(v + BN_EPS);
        scl[tid] = s;
        shf[tid] = be2[tid] - m * s;
    }
    __syncthreads();

    for (int t = blk; t < NB_GIN; t += GRID_GIN) {
        const int base = t * NPB;
        const int n = base + nl;
        const bool valid = n < NN;

        {
            float4 h0 = make_float4(0.f, 0.f, 0.f, 0.f), h1v = h0;
            if (valid) {
                h0  = *(const float4*)&d_h2[(size_t)n * HH + cg];
                h1v = *(const float4*)&d_h2[(size_t)n * HH + cg + 4];
            }
            zst[cg + 0][nl] = h0.x  * scl[cg + 0] + shf[cg + 0];
            zst[cg + 1][nl] = h0.y  * scl[cg + 1] + shf[cg + 1];
            zst[cg + 2][nl] = h0.z  * scl[cg + 2] + shf[cg + 2];
            zst[cg + 3][nl] = h0.w  * scl[cg + 3] + shf[cg + 3];
            zst[cg + 4][nl] = h1v.x * scl[cg + 4] + shf[cg + 4];
            zst[cg + 5][nl] = h1v.y * scl[cg + 5] + shf[cg + 5];
            zst[cg + 6][nl] = h1v.z * scl[cg + 6] + shf[cg + 6];
            zst[cg + 7][nl] = h1v.w * scl[cg + 7] + shf[cg + 7];
        }
        __syncthreads();

        float u[8];
        {
            float4 b0 = *(const float4*)&bf1[cg];
            float4 b1 = *(const float4*)&bf1[cg + 4];
            u[0] = b0.x; u[1] = b0.y; u[2] = b0.z; u[3] = b0.w;
            u[4] = b1.x; u[5] = b1.y; u[6] = b1.z; u[7] = b1.w;
        }
        matmul8(zst, WA, nl, cg, u);
#pragma unroll
        for (int j = 0; j < 8; j++) {
            u[j] = fmaxf(u[j], 0.f);
            ust[cg + j][nl] = u[j];
        }
        __syncthreads();

        const int cg2 = 32 + cg;
        const bool sec = (tid & 3) < 2;
        float o[8], o2[8];
#pragma unroll
        for (int j = 0; j < 8; j++) {
            int c = cg + j;
            o[j] = (c < CC) ? bf2[c] : 0.f;
            int c2 = cg2 + j;
            o2[j] = (sec && c2 < CC) ? bf2[c2] : 0.f;
        }
#pragma unroll
        for (int k = 0; k < HH; k++) {
            float zv = ust[k][nl];
            float4 w0 = *(const float4*)&WB[k][cg];
            float4 w1 = *(const float4*)&WB[k][cg + 4];
            o[0] += zv * w0.x; o[1] += zv * w0.y;
            o[2] += zv * w0.z; o[3] += zv * w0.w;
            o[4] += zv * w1.x; o[5] += zv * w1.y;
            o[6] += zv * w1.z; o[7] += zv * w1.w;
            if (sec) {
                float4 s0 = *(const float4*)&WB[k][cg2];
                float4 s1 = *(const float4*)&WB[k][cg2 + 4];
                o2[0] += zv * s0.x; o2[1] += zv * s0.y;
                o2[2] += zv * s0.z; o2[3] += zv * s0.w;
                o2[4] += zv * s1.x; o2[5] += zv * s1.y;
                o2[6] += zv * s1.z; o2[7] += zv * s1.w;
            }
        }
        if (valid) {
#pragma unroll
            for (int j = 0; j < 8; j++)
                outp[(size_t)n * CC + cg + j] = o[j];
            if (sec) {
#pragma unroll
                for (int j = 0; j < 8; j++) {
                    int c2 = cg2 + j;
                    if (c2 < CC) outp[(size_t)n * CC + c2] = o2[j];
                }
            }
        }
        __syncthreads();
    }
}

// ---------------- launcher ----------------------------------------------------
extern "C" void kernel_launch(void* const* d_in, const int* in_sizes, int n_in,
                              void* d_out, int out_size) {
    const float* x   = (const float*)d_in[0];
    const int*   row = (const int*)  d_in[1];
    const int*   col = (const int*)  d_in[2];
    const float* W1a = (const float*)d_in[3];
    const float* b1a = (const float*)d_in[4];
    const float* W1b = (const float*)d_in[5];
    const float* b1b = (const float*)d_in[6];
    const float* g1  = (const float*)d_in[7];
    const float* be1 = (const float*)d_in[8];
    const float* W2a = (const float*)d_in[9];
    const float* b2a = (const float*)d_in[10];
    const float* W2b = (const float*)d_in[11];
    const float* b2b = (const float*)d_in[12];
    const float* g2  = (const float*)d_in[13];
    const float* be2 = (const float*)d_in[14];
    const float* Wf1 = (const float*)d_in[15];
    const float* bf1 = (const float*)d_in[16];
    const float* Wf2 = (const float*)d_in[17];
    const float* bf2 = (const float*)d_in[18];
    float* out = (float*)d_out;

    static cudaStream_t sA = nullptr;
    static cudaEvent_t  evFork = nullptr, evJoin = nullptr;
    static bool inited = false;
    if (!inited) {
        int lo = 0, hi = 0;
        cudaDeviceGetStreamPriorityRange(&lo, &hi);
        cudaStreamCreateWithPriority(&sA, cudaStreamNonBlocking, hi);
        cudaEventCreateWithFlags(&evFork, cudaEventDisableTiming);
        cudaEventCreateWithFlags(&evJoin, cudaEventDisableTiming);
        inited = true;
    }

    // fork: gemm1 on high-priority sA; CSR build on main stream
    cudaEventRecord(evFork, 0);
    cudaStreamWaitEvent(sA, evFork, 0);

    k_gemm1<<<(NN + GT2 - 1) / GT2, 128, 0, sA>>>(x, W1a);          // #1

    const int eblk1 = (EE + 255) / 256;
    k_hist<<<eblk1, 256, 0, 0>>>(row);                               // #2
    k_csr2<<<GRID_CSR, 256, 0, 0>>>(row, col);                       // #3

    // join
    cudaEventRecord(evJoin, sA);
    cudaStreamWaitEvent(0, evJoin, 0);

    k_gins<<<GRID_GIN, 256, 0, 0>>>(b1a, W1b, b1b, g1, be1,          // #4
                                    W2a, b2a, W2b, b2b, g2, be2,
                                    Wf1, bf1, Wf2, bf2, out);
}